// round 16
// baseline (speedup 1.0000x reference)
#include <cuda_runtime.h>
#include <cstdint>
#include <math.h>

#define BB 4
#define TT 512
#define DD 64
#define KK 192
#define X_ELEMS (BB*TT*DD)
#define GBUF 2048          // 16k x 128 cols floats per G buffer

__device__ float g_F[BB * KK * TT];
__device__ float g_F2[BB * KK * TT];
__device__ float g_X1[BB * TT * DD];
__device__ float g_Cov[BB * DD * DD];   // atomically accumulated Gram
__device__ float g_Mean[BB * DD];       // atomically accumulated column sums
__device__ float g_Kap[BB];             // atomically accumulated row-norm sums
__device__ int   g_Cnt;                 // completion ticket counter

// ---------------------------------------------------------------------------
__global__ void prep_kernel(const float* __restrict__ x, float* __restrict__ Fm) {
    const float EPSf = 1e-8f;
    const float C2 = 7.0710678118654755e-05f;
    const float C3 = 3.5355339059327378e-09f;
    int row = blockIdx.x;
    int d = threadIdx.x;
    float v = x[(row << 6) + d];
    float sp = fmaxf(v, 0.0f) + log1pf(expf(-fabsf(v)));

    float s = sp;
    #pragma unroll
    for (int o = 16; o > 0; o >>= 1) s += __shfl_xor_sync(0xffffffffu, s, o);
    __shared__ float sh[2], sh2[2];
    if ((d & 31) == 0) sh[d >> 5] = s;
    __syncthreads();
    float S = sh[0] + sh[1];
    float p = sp / (S + EPSf);
    p = fmaxf(p, EPSf);
    float s2 = p;
    #pragma unroll
    for (int o = 16; o > 0; o >>= 1) s2 += __shfl_xor_sync(0xffffffffu, s2, o);
    if ((d & 31) == 0) sh2[d >> 5] = s2;
    __syncthreads();
    float S2 = sh2[0] + sh2[1];
    p = p / (S2 + EPSf);

    float sq  = sqrtf(p);
    float inv = 1.0f / sq;
    int b = row >> 9, t = row & 511;
    float* Fb = Fm + b * (KK * TT);
    Fb[d * TT + t]          = sq;
    Fb[(64 + d) * TT + t]   = C2 * inv;
    Fb[(128 + d) * TT + t]  = C3 * (inv * inv * inv);
}

__device__ __forceinline__ float logit_of(float inr) {
    inr = fminf(inr, 1.0f - 1e-6f);
    inr = fmaxf(inr, -1.0f + 1e-6f);
    return -2.0f * acosf(inr);
}

__device__ __forceinline__ void cp_async16(unsigned int saddr, const void* gaddr) {
    asm volatile("cp.async.cg.shared.global [%0], [%1], 16;\n" :: "r"(saddr), "l"(gaddr));
}
__device__ __forceinline__ void cp_commit() {
    asm volatile("cp.async.commit_group;\n" ::: "memory");
}
template<int N>
__device__ __forceinline__ void cp_wait() {
    asm volatile("cp.async.wait_group %0;\n" :: "n"(N) : "memory");
}
__device__ __forceinline__ void barg(int grp) {
    asm volatile("bar.sync %0, 64;" :: "r"(grp + 1) : "memory");
}

__device__ __forceinline__ void load_g_chunk(unsigned int base, const float* __restrict__ Fb,
                                             int c, int buf, int jt0, int ltid) {
    #pragma unroll
    for (int j = 0; j < 8; j++) {
        int i = ltid + j * 64;
        int kl = i >> 5, c4 = i & 31;
        cp_async16(base + (unsigned)((buf * GBUF + kl * 128 + c4 * 4) * 4),
                   Fb + (c * 16 + kl) * TT + jt0 + c4 * 4);
    }
    cp_commit();
}

// ---------------------------------------------------------------------------
// attn: 256 blocks (4 b x 64 strips of 8 rows), 256 threads = 4 groups of 64.
// doStats=1 (final iter): atomic stats + last-block inline phi/kappa finalize.
// doStats=0 (iter 1): zeroes stat accumulators + ticket counter.
// smem floats: sF[1536] | sG[16384] | sI[4128] | sPb[2112] | sRow[8]
// ---------------------------------------------------------------------------
__global__ void __launch_bounds__(256, 2) attn_kernel(
    const float* __restrict__ Fm, const float* __restrict__ xin,
    float* __restrict__ xout, const float* __restrict__ rsp,
    float* __restrict__ Fout, int doStats) {
    extern __shared__ float smem[];
    float* sF   = smem;                 // 1536
    float* sG   = smem + 1536;          // 16384
    float* sI   = sG + 16384;           // 4128
    float* sPb  = sI + 8 * 516;         // 2112
    float* sRow = sPb + 2112;           // 8

    int b  = blockIdx.x >> 6;
    int rb = blockIdx.x & 63;
    int r0 = rb * 8;
    const float* Fb = Fm + b * KK * TT;
    const float* xb = xin + b * TT * DD;
    int tid  = threadIdx.x;
    int grp  = tid >> 6;
    int ltid = tid & 63;
    int rowg = ltid >> 5;     // 0..1
    int colg = ltid & 31;

    if (!doStats) {
        // zero stat accumulators + counter for the next launch
        int base = blockIdx.x * 66;
        int j = base + tid;
        if (tid < 66) {
            if (j < BB * DD * DD) g_Cov[j] = 0.0f;
            int i2 = j - BB * DD * DD;
            if (i2 >= 0 && i2 < BB * DD) g_Mean[i2] = 0.0f;
            int i3 = i2 - BB * DD;
            if (i3 >= 0 && i3 < BB) g_Kap[i3] = 0.0f;
        }
        if (blockIdx.x == 0 && tid == 66) g_Cnt = 0;
    }

    for (int i = tid; i < KK * 8; i += 256) {
        int k = i >> 3, r = i & 7;
        float v = Fb[k * TT + r0 + r];
        sF[i] = (k >= 128) ? -v : v;
    }
    __syncthreads();

    float* myG = sG + grp * 2 * GBUF;
    unsigned int myG_base = (unsigned int)__cvta_generic_to_shared(myG);
    const int jt0 = grp * 128;
    const float4* sF4 = reinterpret_cast<const float4*>(sF);

    // ---------------- GEMM1: full-K inner products, own column quarter ------
    float acc[4][4];
    #pragma unroll
    for (int i = 0; i < 4; i++)
        #pragma unroll
        for (int j = 0; j < 4; j++) acc[i][j] = 0.0f;

    load_g_chunk(myG_base, Fb, 0, 0, jt0, ltid);
    #pragma unroll 1
    for (int c = 0; c < 12; c++) {
        if (c < 11) {
            load_g_chunk(myG_base, Fb, c + 1, (c + 1) & 1, jt0, ltid);
            cp_wait<1>();
        } else {
            cp_wait<0>();
        }
        barg(grp);
        const float4* buf4 = reinterpret_cast<const float4*>(myG + (c & 1) * GBUF);
        int kbase = c * 16;
        #pragma unroll
        for (int kk = 0; kk < 16; kk++) {
            float4 fa = sF4[((kbase + kk) << 1) + rowg];
            float4 gb = buf4[(kk << 5) + colg];
            acc[0][0] += fa.x * gb.x; acc[0][1] += fa.x * gb.y;
            acc[0][2] += fa.x * gb.z; acc[0][3] += fa.x * gb.w;
            acc[1][0] += fa.y * gb.x; acc[1][1] += fa.y * gb.y;
            acc[1][2] += fa.y * gb.z; acc[1][3] += fa.y * gb.w;
            acc[2][0] += fa.z * gb.x; acc[2][1] += fa.z * gb.y;
            acc[2][2] += fa.z * gb.z; acc[2][3] += fa.z * gb.w;
            acc[3][0] += fa.w * gb.x; acc[3][1] += fa.w * gb.y;
            acc[3][2] += fa.w * gb.z; acc[3][3] += fa.w * gb.w;
        }
        barg(grp);
    }

    #pragma unroll
    for (int i = 0; i < 4; i++) {
        float4 o;
        o.x = logit_of(acc[i][0]);
        o.y = logit_of(acc[i][1]);
        o.z = logit_of(acc[i][2]);
        o.w = logit_of(acc[i][3]);
        *reinterpret_cast<float4*>(&sI[(rowg * 4 + i) * 516 + jt0 + colg * 4]) = o;
    }
    __syncthreads();

    // ---------------- softmax ----------------
    {
        int r = tid >> 5, sub = tid & 31;
        float m = -3.4e38f;
        for (int c = sub; c < TT; c += 32) m = fmaxf(m, sI[r * 516 + c]);
        #pragma unroll
        for (int o = 16; o > 0; o >>= 1) m = fmaxf(m, __shfl_xor_sync(0xffffffffu, m, o));
        float sum = 0.0f;
        for (int c = sub; c < TT; c += 32) {
            float e = __expf(sI[r * 516 + c] - m);
            sI[r * 516 + c] = e;
            sum += e;
        }
        #pragma unroll
        for (int o = 16; o > 0; o >>= 1) sum += __shfl_xor_sync(0xffffffffu, sum, o);
        if (sub == 0) sRow[r] = 1.0f / sum;
    }
    __syncthreads();

    // ---------------- GEMM2 ----------------
    float acc2[4][2];
    #pragma unroll
    for (int i = 0; i < 4; i++) { acc2[i][0] = 0.0f; acc2[i][1] = 0.0f; }
    float* sX = sG + grp * 2176;   // [32][68]
    unsigned int sX_base = (unsigned int)__cvta_generic_to_shared(sX);
    int kb = grp * 32;

    #pragma unroll 1
    for (int kt = 0; kt < TT; kt += 128) {
        barg(grp);
        #pragma unroll
        for (int j = 0; j < 8; j++) {
            int i = ltid + j * 64;
            int t = i >> 4, d4 = i & 15;
            cp_async16(sX_base + (unsigned)((t * 68 + d4 * 4) * 4),
                       xb + (kt + kb + t) * 64 + d4 * 4);
        }
        cp_commit();
        cp_wait<0>();
        barg(grp);
        #pragma unroll 4
        for (int kk = 0; kk < 32; kk++) {
            int kw = kt + kb + kk;
            float w0 = sI[(rowg * 4 + 0) * 516 + kw];
            float w1 = sI[(rowg * 4 + 1) * 516 + kw];
            float w2 = sI[(rowg * 4 + 2) * 516 + kw];
            float w3 = sI[(rowg * 4 + 3) * 516 + kw];
            float2 xv = *reinterpret_cast<const float2*>(&sX[kk * 68 + colg * 2]);
            acc2[0][0] += w0 * xv.x; acc2[0][1] += w0 * xv.y;
            acc2[1][0] += w1 * xv.x; acc2[1][1] += w1 * xv.y;
            acc2[2][0] += w2 * xv.x; acc2[2][1] += w2 * xv.y;
            acc2[3][0] += w3 * xv.x; acc2[3][1] += w3 * xv.y;
        }
    }
    #pragma unroll
    for (int i = 0; i < 4; i++) {
        float2 o = make_float2(acc2[i][0], acc2[i][1]);
        *reinterpret_cast<float2*>(&sPb[grp * 528 + (rowg * 4 + i) * 66 + colg * 2]) = o;
    }
    __syncthreads();

    int r  = tid >> 5, c2 = tid & 31;
    float xn0, xn1;
    {
        float2 s0 = *reinterpret_cast<const float2*>(&sPb[0 * 528 + r * 66 + c2 * 2]);
        float2 s1 = *reinterpret_cast<const float2*>(&sPb[1 * 528 + r * 66 + c2 * 2]);
        float2 s2 = *reinterpret_cast<const float2*>(&sPb[2 * 528 + r * 66 + c2 * 2]);
        float2 s3 = *reinterpret_cast<const float2*>(&sPb[3 * 528 + r * 66 + c2 * 2]);
        float a = 0.01f * rsp[0];
        float invs = sRow[r];
        int trow = r0 + r;
        float2 xo = *reinterpret_cast<const float2*>(&xb[trow * 64 + c2 * 2]);
        float xa0 = (s0.x + s1.x + s2.x + s3.x) * invs;
        float xa1 = (s0.y + s1.y + s2.y + s3.y) * invs;
        float x10 = 0.5f * xo.x + 0.5f * xa0;
        float x11 = 0.5f * xo.y + 0.5f * xa1;
        xn0 = x10 + a * (xa0 - x10);
        xn1 = x11 + a * (xa1 - x11);
        *reinterpret_cast<float2*>(&xout[b * TT * DD + trow * 64 + c2 * 2]) =
            make_float2(xn0, xn1);

        if (Fout != nullptr) {
            const float EPSf = 1e-8f;
            const float C2c = 7.0710678118654755e-05f;
            const float C3c = 3.5355339059327378e-09f;
            float sp0 = fmaxf(xn0, 0.0f) + log1pf(expf(-fabsf(xn0)));
            float sp1 = fmaxf(xn1, 0.0f) + log1pf(expf(-fabsf(xn1)));
            float s = sp0 + sp1;
            #pragma unroll
            for (int o = 16; o > 0; o >>= 1) s += __shfl_xor_sync(0xffffffffu, s, o);
            float p0 = fmaxf(sp0 / (s + EPSf), EPSf);
            float p1 = fmaxf(sp1 / (s + EPSf), EPSf);
            float s2n = p0 + p1;
            #pragma unroll
            for (int o = 16; o > 0; o >>= 1) s2n += __shfl_xor_sync(0xffffffffu, s2n, o);
            float rs2 = 1.0f / (s2n + EPSf);
            p0 *= rs2; p1 *= rs2;
            float sq0 = sqrtf(p0), iv0 = 1.0f / sq0;
            float sq1 = sqrtf(p1), iv1 = 1.0f / sq1;
            float* Fo = Fout + b * KK * TT;
            int d0 = c2 * 2;
            Fo[d0 * TT + trow]            = sq0;
            Fo[(64 + d0) * TT + trow]     = C2c * iv0;
            Fo[(128 + d0) * TT + trow]    = C3c * (iv0 * iv0 * iv0);
            Fo[(d0 + 1) * TT + trow]       = sq1;
            Fo[(64 + d0 + 1) * TT + trow]  = C2c * iv1;
            Fo[(128 + d0 + 1) * TT + trow] = C3c * (iv1 * iv1 * iv1);
        }
    }

    // ---------------- fused statistics + last-block finalization ------------
    if (doStats) {
        __syncthreads();                 // everyone done reading sPb/sRow
        float* sXn = sPb;                // [8][68]
        sXn[r * 68 + c2 * 2]     = xn0;
        sXn[r * 68 + c2 * 2 + 1] = xn1;
        float sq = xn0 * xn0 + xn1 * xn1;
        #pragma unroll
        for (int o = 16; o > 0; o >>= 1) sq += __shfl_xor_sync(0xffffffffu, sq, o);
        if (c2 == 0) sRow[r] = sqrtf(sq);
        __syncthreads();
        if (tid < 64) {
            float s = 0.0f;
            #pragma unroll
            for (int t = 0; t < 8; t++) s += sXn[t * 68 + tid];
            atomicAdd(&g_Mean[b * 64 + tid], s);
        }
        if (tid == 64) {
            float k = 0.0f;
            #pragma unroll
            for (int t = 0; t < 8; t++) k += sRow[t];
            atomicAdd(&g_Kap[b], k);
        }
        int td = tid >> 4, te = tid & 15;
        int d0 = td * 4, e0 = te * 4;
        float a4[4][4];
        #pragma unroll
        for (int i = 0; i < 4; i++)
            #pragma unroll
            for (int j = 0; j < 4; j++) a4[i][j] = 0.0f;
        #pragma unroll
        for (int t = 0; t < 8; t++) {
            float4 dv = *reinterpret_cast<const float4*>(&sXn[t * 68 + d0]);
            float4 ev = *reinterpret_cast<const float4*>(&sXn[t * 68 + e0]);
            a4[0][0] += dv.x*ev.x; a4[0][1] += dv.x*ev.y; a4[0][2] += dv.x*ev.z; a4[0][3] += dv.x*ev.w;
            a4[1][0] += dv.y*ev.x; a4[1][1] += dv.y*ev.y; a4[1][2] += dv.y*ev.z; a4[1][3] += dv.y*ev.w;
            a4[2][0] += dv.z*ev.x; a4[2][1] += dv.z*ev.y; a4[2][2] += dv.z*ev.z; a4[2][3] += dv.z*ev.w;
            a4[3][0] += dv.w*ev.x; a4[3][1] += dv.w*ev.y; a4[3][2] += dv.w*ev.z; a4[3][3] += dv.w*ev.w;
        }
        float* cb = g_Cov + b * 4096;
        #pragma unroll
        for (int i = 0; i < 4; i++)
            #pragma unroll
            for (int j = 0; j < 4; j++)
                atomicAdd(&cb[(d0 + i) * 64 + e0 + j], a4[i][j]);

        // -------- ticket: last block finalizes phi & kappa for all batches --
        __threadfence();
        __shared__ int isLast;
        if (tid == 0) {
            int t = atomicAdd(&g_Cnt, 1);
            isLast = (t == 255);
        }
        __syncthreads();
        if (isLast) {
            const float invT = 1.0f / 512.0f;
            float* sVar = sXn;        // reuse smem: [4][64] var then m
            float* sM   = sXn + 256;
            // tid 0..255 -> (batch bb = tid>>6, dim dd = tid&63)
            {
                int bb = tid >> 6, dd = tid & 63;
                float mm = __ldcg(&g_Mean[bb * 64 + dd]) * invT;
                sM[bb * 64 + dd] = mm;
                float cv = (__ldcg(&g_Cov[bb * 4096 + dd * 65]) - 512.0f * mm * mm) * invT;
                sVar[bb * 64 + dd] = fmaxf(cv, 1e-8f);
            }
            __syncthreads();
            #pragma unroll 1
            for (int bb = 0; bb < BB; bb++) {
                const float* cbv = g_Cov + bb * 4096;
                const float* mv = sM + bb * 64;
                const float* vv = sVar + bb * 64;
                float acc1 = 0.0f;
                #pragma unroll
                for (int j = 0; j < 16; j++) {
                    int i = tid + j * 256;
                    int d = i >> 6, e = i & 63;
                    if (d != e) {
                        float cv = (__ldcg(&cbv[i]) - 512.0f * mv[d] * mv[e]) * invT;
                        float denom = fmaxf(sqrtf(vv[d] * vv[e]), 1e-8f);
                        float c = fminf(fmaxf(cv / denom, -1.0f), 1.0f);
                        acc1 += fabsf(c);
                    }
                }
                #pragma unroll
                for (int o = 16; o > 0; o >>= 1) acc1 += __shfl_xor_sync(0xffffffffu, acc1, o);
                if ((tid & 31) == 0) sRow[tid >> 5] = acc1;   // sRow has 8 slots
                __syncthreads();
                if (tid == 0) {
                    float p = 0.0f;
                    #pragma unroll
                    for (int w = 0; w < 8; w++) p += sRow[w];
                    xout[X_ELEMS + bb] = p * (1.0f / 4096.0f);
                    xout[X_ELEMS + BB + bb] = __ldcg(&g_Kap[bb]) * (1.0f / 512.0f);
                }
                __syncthreads();
            }
        }
    }
}

// ---------------------------------------------------------------------------
extern "C" void kernel_launch(void* const* d_in, const int* in_sizes, int n_in,
                              void* d_out, int out_size) {
    (void)in_sizes; (void)n_in; (void)out_size;
    const float* x0 = (const float*)d_in[0];
    const float* rs = (const float*)d_in[1];
    float* out = (float*)d_out;

    float *pF, *pF2, *pX1;
    cudaGetSymbolAddress((void**)&pF, g_F);
    cudaGetSymbolAddress((void**)&pF2, g_F2);
    cudaGetSymbolAddress((void**)&pX1, g_X1);

    const size_t attnSmem = (size_t)(1536 + 16384 + 8 * 516 + 2112 + 8) * sizeof(float); // 96,672 B
    cudaFuncSetAttribute(attn_kernel, cudaFuncAttributeMaxDynamicSharedMemorySize, (int)attnSmem);

    prep_kernel<<<BB * TT, 64>>>(x0, pF);
    attn_kernel<<<256, 256, attnSmem>>>(pF, x0, pX1, rs, pF2, 0);       // iter 1 + prep fusion + zeroing
    attn_kernel<<<256, 256, attnSmem>>>(pF2, pX1, out, rs, nullptr, 1); // iter 2 + stats + inline finalize
}

// round 17
// speedup vs baseline: 1.4582x; 1.4582x over previous
#include <cuda_runtime.h>
#include <cstdint>
#include <math.h>

#define BB 4
#define TT 512
#define DD 64
#define KK 192
#define X_ELEMS (BB*TT*DD)
#define GBUF 2048          // 16k x 128 cols floats per G buffer

__device__ float g_F[BB * KK * TT];
__device__ float g_F2[BB * KK * TT];
__device__ float g_X1[BB * TT * DD];
__device__ float g_Cov[BB * DD * DD];   // atomically accumulated Gram
__device__ float g_Mean[BB * DD];       // atomically accumulated column sums
__device__ float g_Kap[BB];             // atomically accumulated row-norm sums

// ---------------------------------------------------------------------------
__global__ void prep_kernel(const float* __restrict__ x, float* __restrict__ Fm) {
    const float EPSf = 1e-8f;
    const float C2 = 7.0710678118654755e-05f;
    const float C3 = 3.5355339059327378e-09f;
    int row = blockIdx.x;
    int d = threadIdx.x;
    float v = x[(row << 6) + d];
    float sp = fmaxf(v, 0.0f) + log1pf(expf(-fabsf(v)));

    float s = sp;
    #pragma unroll
    for (int o = 16; o > 0; o >>= 1) s += __shfl_xor_sync(0xffffffffu, s, o);
    __shared__ float sh[2], sh2[2];
    if ((d & 31) == 0) sh[d >> 5] = s;
    __syncthreads();
    float S = sh[0] + sh[1];
    float p = sp / (S + EPSf);
    p = fmaxf(p, EPSf);
    float s2 = p;
    #pragma unroll
    for (int o = 16; o > 0; o >>= 1) s2 += __shfl_xor_sync(0xffffffffu, s2, o);
    if ((d & 31) == 0) sh2[d >> 5] = s2;
    __syncthreads();
    float S2 = sh2[0] + sh2[1];
    p = p / (S2 + EPSf);

    float sq  = sqrtf(p);
    float inv = 1.0f / sq;
    int b = row >> 9, t = row & 511;
    float* Fb = Fm + b * (KK * TT);
    Fb[d * TT + t]          = sq;
    Fb[(64 + d) * TT + t]   = C2 * inv;
    Fb[(128 + d) * TT + t]  = C3 * (inv * inv * inv);
}

__device__ __forceinline__ float logit_of(float inr) {
    inr = fminf(inr, 1.0f - 1e-6f);
    inr = fmaxf(inr, -1.0f + 1e-6f);
    return -2.0f * acosf(inr);
}

__device__ __forceinline__ void cp_async16(unsigned int saddr, const void* gaddr) {
    asm volatile("cp.async.cg.shared.global [%0], [%1], 16;\n" :: "r"(saddr), "l"(gaddr));
}
__device__ __forceinline__ void cp_commit() {
    asm volatile("cp.async.commit_group;\n" ::: "memory");
}
template<int N>
__device__ __forceinline__ void cp_wait() {
    asm volatile("cp.async.wait_group %0;\n" :: "n"(N) : "memory");
}
__device__ __forceinline__ void barg(int grp) {
    asm volatile("bar.sync %0, 64;" :: "r"(grp + 1) : "memory");
}

__device__ __forceinline__ void load_g_chunk(unsigned int base, const float* __restrict__ Fb,
                                             int c, int buf, int jt0, int ltid) {
    #pragma unroll
    for (int j = 0; j < 8; j++) {
        int i = ltid + j * 64;
        int kl = i >> 5, c4 = i & 31;
        cp_async16(base + (unsigned)((buf * GBUF + kl * 128 + c4 * 4) * 4),
                   Fb + (c * 16 + kl) * TT + jt0 + c4 * 4);
    }
    cp_commit();
}

// ---------------------------------------------------------------------------
// attn: 256 blocks (4 b x 64 strips of 8 rows), 256 threads = 4 groups of 64.
// doStats=1 (final iter): Gram/mean/kappa accumulated via atomicAdd; zeroes
//                         out phi slots for phik's atomic combine.
// doStats=0 (iter 1): zeroes stat accumulators (ordered before iter 2).
// smem floats: sF[1536] | sG[16384] | sI[4128] | sPb[2112] | sRow[8]
// ---------------------------------------------------------------------------
__global__ void __launch_bounds__(256, 2) attn_kernel(
    const float* __restrict__ Fm, const float* __restrict__ xin,
    float* __restrict__ xout, const float* __restrict__ rsp,
    float* __restrict__ Fout, int doStats) {
    extern __shared__ float smem[];
    float* sF   = smem;                 // 1536
    float* sG   = smem + 1536;          // 16384
    float* sI   = sG + 16384;           // 4128
    float* sPb  = sI + 8 * 516;         // 2112
    float* sRow = sPb + 2112;           // 8

    int b  = blockIdx.x >> 6;
    int rb = blockIdx.x & 63;
    int r0 = rb * 8;
    const float* Fb = Fm + b * KK * TT;
    const float* xb = xin + b * TT * DD;
    int tid  = threadIdx.x;
    int grp  = tid >> 6;
    int ltid = tid & 63;
    int rowg = ltid >> 5;     // 0..1
    int colg = ltid & 31;

    if (!doStats) {
        // zero stat accumulators for the next launch (strictly ordered)
        int j = blockIdx.x * 66 + tid;
        if (tid < 66) {
            if (j < BB * DD * DD) g_Cov[j] = 0.0f;
            int i2 = j - BB * DD * DD;
            if (i2 >= 0 && i2 < BB * DD) g_Mean[i2] = 0.0f;
            int i3 = i2 - BB * DD;
            if (i3 >= 0 && i3 < BB) g_Kap[i3] = 0.0f;
        }
    } else {
        // zero the phi output slots for phik's atomic combine
        if (blockIdx.x == 0 && tid < BB) xout[X_ELEMS + tid] = 0.0f;
    }

    for (int i = tid; i < KK * 8; i += 256) {
        int k = i >> 3, r = i & 7;
        float v = Fb[k * TT + r0 + r];
        sF[i] = (k >= 128) ? -v : v;
    }
    __syncthreads();

    float* myG = sG + grp * 2 * GBUF;
    unsigned int myG_base = (unsigned int)__cvta_generic_to_shared(myG);
    const int jt0 = grp * 128;
    const float4* sF4 = reinterpret_cast<const float4*>(sF);

    // ---------------- GEMM1: full-K inner products, own column quarter ------
    float acc[4][4];
    #pragma unroll
    for (int i = 0; i < 4; i++)
        #pragma unroll
        for (int j = 0; j < 4; j++) acc[i][j] = 0.0f;

    load_g_chunk(myG_base, Fb, 0, 0, jt0, ltid);
    #pragma unroll 1
    for (int c = 0; c < 12; c++) {
        if (c < 11) {
            load_g_chunk(myG_base, Fb, c + 1, (c + 1) & 1, jt0, ltid);
            cp_wait<1>();
        } else {
            cp_wait<0>();
        }
        barg(grp);
        const float4* buf4 = reinterpret_cast<const float4*>(myG + (c & 1) * GBUF);
        int kbase = c * 16;
        #pragma unroll
        for (int kk = 0; kk < 16; kk++) {
            float4 fa = sF4[((kbase + kk) << 1) + rowg];
            float4 gb = buf4[(kk << 5) + colg];
            acc[0][0] += fa.x * gb.x; acc[0][1] += fa.x * gb.y;
            acc[0][2] += fa.x * gb.z; acc[0][3] += fa.x * gb.w;
            acc[1][0] += fa.y * gb.x; acc[1][1] += fa.y * gb.y;
            acc[1][2] += fa.y * gb.z; acc[1][3] += fa.y * gb.w;
            acc[2][0] += fa.z * gb.x; acc[2][1] += fa.z * gb.y;
            acc[2][2] += fa.z * gb.z; acc[2][3] += fa.z * gb.w;
            acc[3][0] += fa.w * gb.x; acc[3][1] += fa.w * gb.y;
            acc[3][2] += fa.w * gb.z; acc[3][3] += fa.w * gb.w;
        }
        barg(grp);
    }

    #pragma unroll
    for (int i = 0; i < 4; i++) {
        float4 o;
        o.x = logit_of(acc[i][0]);
        o.y = logit_of(acc[i][1]);
        o.z = logit_of(acc[i][2]);
        o.w = logit_of(acc[i][3]);
        *reinterpret_cast<float4*>(&sI[(rowg * 4 + i) * 516 + jt0 + colg * 4]) = o;
    }
    __syncthreads();

    // ---------------- softmax ----------------
    {
        int r = tid >> 5, sub = tid & 31;
        float m = -3.4e38f;
        for (int c = sub; c < TT; c += 32) m = fmaxf(m, sI[r * 516 + c]);
        #pragma unroll
        for (int o = 16; o > 0; o >>= 1) m = fmaxf(m, __shfl_xor_sync(0xffffffffu, m, o));
        float sum = 0.0f;
        for (int c = sub; c < TT; c += 32) {
            float e = __expf(sI[r * 516 + c] - m);
            sI[r * 516 + c] = e;
            sum += e;
        }
        #pragma unroll
        for (int o = 16; o > 0; o >>= 1) sum += __shfl_xor_sync(0xffffffffu, sum, o);
        if (sub == 0) sRow[r] = 1.0f / sum;
    }
    __syncthreads();

    // ---------------- GEMM2: double-buffered X tiles ----------
    float acc2[4][2];
    #pragma unroll
    for (int i = 0; i < 4; i++) { acc2[i][0] = 0.0f; acc2[i][1] = 0.0f; }
    float* sXg = sG + grp * 4096;        // 2 buffers x [32][64]
    unsigned int sX_base = (unsigned int)__cvta_generic_to_shared(sXg);
    int kb = grp * 32;

    // prologue: tile 0 -> buf 0
    #pragma unroll
    for (int j = 0; j < 8; j++) {
        int i = ltid + j * 64;
        int t = i >> 4, d4 = i & 15;
        cp_async16(sX_base + (unsigned)((t * 64 + d4 * 4) * 4),
                   xb + (kb + t) * 64 + d4 * 4);
    }
    cp_commit();

    #pragma unroll 1
    for (int t4 = 0; t4 < 4; t4++) {
        if (t4 < 3) {
            int nb = (t4 + 1) & 1;
            #pragma unroll
            for (int j = 0; j < 8; j++) {
                int i = ltid + j * 64;
                int t = i >> 4, d4 = i & 15;
                cp_async16(sX_base + (unsigned)((nb * 2048 + t * 64 + d4 * 4) * 4),
                           xb + ((t4 + 1) * 128 + kb + t) * 64 + d4 * 4);
            }
            cp_commit();
            cp_wait<1>();
        } else {
            cp_wait<0>();
        }
        barg(grp);
        const float* sX = sXg + (t4 & 1) * 2048;
        int kt = t4 * 128;
        #pragma unroll 4
        for (int kk = 0; kk < 32; kk++) {
            int kw = kt + kb + kk;
            float w0 = sI[(rowg * 4 + 0) * 516 + kw];
            float w1 = sI[(rowg * 4 + 1) * 516 + kw];
            float w2 = sI[(rowg * 4 + 2) * 516 + kw];
            float w3 = sI[(rowg * 4 + 3) * 516 + kw];
            float2 xv = *reinterpret_cast<const float2*>(&sX[kk * 64 + colg * 2]);
            acc2[0][0] += w0 * xv.x; acc2[0][1] += w0 * xv.y;
            acc2[1][0] += w1 * xv.x; acc2[1][1] += w1 * xv.y;
            acc2[2][0] += w2 * xv.x; acc2[2][1] += w2 * xv.y;
            acc2[3][0] += w3 * xv.x; acc2[3][1] += w3 * xv.y;
        }
        barg(grp);
    }
    #pragma unroll
    for (int i = 0; i < 4; i++) {
        float2 o = make_float2(acc2[i][0], acc2[i][1]);
        *reinterpret_cast<float2*>(&sPb[grp * 528 + (rowg * 4 + i) * 66 + colg * 2]) = o;
    }
    __syncthreads();

    int r  = tid >> 5, c2 = tid & 31;
    float xn0, xn1;
    {
        float2 s0 = *reinterpret_cast<const float2*>(&sPb[0 * 528 + r * 66 + c2 * 2]);
        float2 s1 = *reinterpret_cast<const float2*>(&sPb[1 * 528 + r * 66 + c2 * 2]);
        float2 s2 = *reinterpret_cast<const float2*>(&sPb[2 * 528 + r * 66 + c2 * 2]);
        float2 s3 = *reinterpret_cast<const float2*>(&sPb[3 * 528 + r * 66 + c2 * 2]);
        float a = 0.01f * rsp[0];
        float invs = sRow[r];
        int trow = r0 + r;
        float2 xo = *reinterpret_cast<const float2*>(&xb[trow * 64 + c2 * 2]);
        float xa0 = (s0.x + s1.x + s2.x + s3.x) * invs;
        float xa1 = (s0.y + s1.y + s2.y + s3.y) * invs;
        float x10 = 0.5f * xo.x + 0.5f * xa0;
        float x11 = 0.5f * xo.y + 0.5f * xa1;
        xn0 = x10 + a * (xa0 - x10);
        xn1 = x11 + a * (xa1 - x11);
        *reinterpret_cast<float2*>(&xout[b * TT * DD + trow * 64 + c2 * 2]) =
            make_float2(xn0, xn1);

        if (Fout != nullptr) {
            const float EPSf = 1e-8f;
            const float C2c = 7.0710678118654755e-05f;
            const float C3c = 3.5355339059327378e-09f;
            float sp0 = fmaxf(xn0, 0.0f) + log1pf(expf(-fabsf(xn0)));
            float sp1 = fmaxf(xn1, 0.0f) + log1pf(expf(-fabsf(xn1)));
            float s = sp0 + sp1;
            #pragma unroll
            for (int o = 16; o > 0; o >>= 1) s += __shfl_xor_sync(0xffffffffu, s, o);
            float p0 = fmaxf(sp0 / (s + EPSf), EPSf);
            float p1 = fmaxf(sp1 / (s + EPSf), EPSf);
            float s2n = p0 + p1;
            #pragma unroll
            for (int o = 16; o > 0; o >>= 1) s2n += __shfl_xor_sync(0xffffffffu, s2n, o);
            float rs2 = 1.0f / (s2n + EPSf);
            p0 *= rs2; p1 *= rs2;
            float sq0 = sqrtf(p0), iv0 = 1.0f / sq0;
            float sq1 = sqrtf(p1), iv1 = 1.0f / sq1;
            float* Fo = Fout + b * KK * TT;
            int d0 = c2 * 2;
            Fo[d0 * TT + trow]            = sq0;
            Fo[(64 + d0) * TT + trow]     = C2c * iv0;
            Fo[(128 + d0) * TT + trow]    = C3c * (iv0 * iv0 * iv0);
            Fo[(d0 + 1) * TT + trow]       = sq1;
            Fo[(64 + d0 + 1) * TT + trow]  = C2c * iv1;
            Fo[(128 + d0 + 1) * TT + trow] = C3c * (iv1 * iv1 * iv1);
        }
    }

    // ---------------- fused statistics (final iteration): atomic accumulate --
    if (doStats) {
        __syncthreads();                 // everyone done reading sPb/sRow
        float* sXn = sPb;                // [8][68]
        sXn[r * 68 + c2 * 2]     = xn0;
        sXn[r * 68 + c2 * 2 + 1] = xn1;
        float sq = xn0 * xn0 + xn1 * xn1;
        #pragma unroll
        for (int o = 16; o > 0; o >>= 1) sq += __shfl_xor_sync(0xffffffffu, sq, o);
        if (c2 == 0) sRow[r] = sqrtf(sq);
        __syncthreads();
        if (tid < 64) {
            float s = 0.0f;
            #pragma unroll
            for (int t = 0; t < 8; t++) s += sXn[t * 68 + tid];
            atomicAdd(&g_Mean[b * 64 + tid], s);
        }
        if (tid == 64) {
            float k = 0.0f;
            #pragma unroll
            for (int t = 0; t < 8; t++) k += sRow[t];
            atomicAdd(&g_Kap[b], k);
        }
        int td = tid >> 4, te = tid & 15;
        int d0 = td * 4, e0 = te * 4;
        float a4[4][4];
        #pragma unroll
        for (int i = 0; i < 4; i++)
            #pragma unroll
            for (int j = 0; j < 4; j++) a4[i][j] = 0.0f;
        #pragma unroll
        for (int t = 0; t < 8; t++) {
            float4 dv = *reinterpret_cast<const float4*>(&sXn[t * 68 + d0]);
            float4 ev = *reinterpret_cast<const float4*>(&sXn[t * 68 + e0]);
            a4[0][0] += dv.x*ev.x; a4[0][1] += dv.x*ev.y; a4[0][2] += dv.x*ev.z; a4[0][3] += dv.x*ev.w;
            a4[1][0] += dv.y*ev.x; a4[1][1] += dv.y*ev.y; a4[1][2] += dv.y*ev.z; a4[1][3] += dv.y*ev.w;
            a4[2][0] += dv.z*ev.x; a4[2][1] += dv.z*ev.y; a4[2][2] += dv.z*ev.z; a4[2][3] += dv.z*ev.w;
            a4[3][0] += dv.w*ev.x; a4[3][1] += dv.w*ev.y; a4[3][2] += dv.w*ev.z; a4[3][3] += dv.w*ev.w;
        }
        float* cb = g_Cov + b * 4096;
        #pragma unroll
        for (int i = 0; i < 4; i++)
            #pragma unroll
            for (int j = 0; j < 4; j++)
                atomicAdd(&cb[(d0 + i) * 64 + e0 + j], a4[i][j]);
    }
}

// ---------------------------------------------------------------------------
// phik: grid (16 slabs, 4 batches) x 256 thr; atomic-combined phi.
// ---------------------------------------------------------------------------
__global__ void __launch_bounds__(256) phik_kernel(
    float* __restrict__ out_phi, float* __restrict__ out_kappa) {
    int slab = blockIdx.x;      // 0..15
    int b = blockIdx.y;
    int tid = threadIdx.x;
    __shared__ float m[64], var[64];
    __shared__ float red[8];
    const float invT = 1.0f / 512.0f;
    const float* cb = g_Cov + b * 4096;

    if (tid < 64) {
        float mm = g_Mean[b * 64 + tid] * invT;
        m[tid] = mm;
        float cv = (cb[tid * 65] - 512.0f * mm * mm) * invT;
        var[tid] = fmaxf(cv, 1e-8f);
    }
    __syncthreads();

    int i = slab * 256 + tid;
    int d = i >> 6, e = i & 63;
    float acc = 0.0f;
    if (d != e) {
        float cv = (cb[i] - 512.0f * m[d] * m[e]) * invT;
        float denom = fmaxf(sqrtf(var[d] * var[e]), 1e-8f);
        float c = fminf(fmaxf(cv / denom, -1.0f), 1.0f);
        acc = fabsf(c);
    }
    #pragma unroll
    for (int o = 16; o > 0; o >>= 1) acc += __shfl_xor_sync(0xffffffffu, acc, o);
    if ((tid & 31) == 0) red[tid >> 5] = acc;
    __syncthreads();
    if (tid == 0) {
        float p = 0.0f;
        #pragma unroll
        for (int w = 0; w < 8; w++) p += red[w];
        atomicAdd(&out_phi[b], p * (1.0f / 4096.0f));
        if (slab == 0) out_kappa[b] = g_Kap[b] * (1.0f / 512.0f);
    }
}

// ---------------------------------------------------------------------------
extern "C" void kernel_launch(void* const* d_in, const int* in_sizes, int n_in,
                              void* d_out, int out_size) {
    (void)in_sizes; (void)n_in; (void)out_size;
    const float* x0 = (const float*)d_in[0];
    const float* rs = (const float*)d_in[1];
    float* out = (float*)d_out;

    float *pF, *pF2, *pX1;
    cudaGetSymbolAddress((void**)&pF, g_F);
    cudaGetSymbolAddress((void**)&pF2, g_F2);
    cudaGetSymbolAddress((void**)&pX1, g_X1);

    const size_t attnSmem = (size_t)(1536 + 16384 + 8 * 516 + 2112 + 8) * sizeof(float); // 96,672 B
    cudaFuncSetAttribute(attn_kernel, cudaFuncAttributeMaxDynamicSharedMemorySize, (int)attnSmem);

    prep_kernel<<<BB * TT, 64>>>(x0, pF);
    attn_kernel<<<256, 256, attnSmem>>>(pF, x0, pX1, rs, pF2, 0);       // iter 1 + prep fusion + zeroing
    attn_kernel<<<256, 256, attnSmem>>>(pF2, pX1, out, rs, nullptr, 1); // iter 2 + atomic stats
    phik_kernel<<<dim3(16, BB), 256>>>(out + X_ELEMS, out + X_ELEMS + BB);
}